// round 9
// baseline (speedup 1.0000x reference)
#include <cuda_runtime.h>
#include <mma.h>
#include <math.h>

using namespace nvcuda;

typedef unsigned long long ull;

// Problem dims (fixed by setup_inputs)
#define BATCH 256
#define DM    512
#define NN    1024
#define KTOT  (2*NN)

// Phase-1 tiling
#define BT 32
#define NT 32
#define DC 64
#define ZSPLIT 8
#define DPER (DM / ZSPLIT)       // 64 == DC
#define P1_THREADS 256

// Phase-2 (wmma 3xTF32 GEMM) tiling
#define GBM 32                   // batch rows per block
#define GBN 32                   // out features per block
#define GBK 32                   // k window
#define GLD 40                   // smem row stride (floats, mult of 4, 16B-aligned rows)
#define GSPLITK 4
#define GKCHUNK (KTOT / GSPLITK) // 512 (never crosses cos/sin boundary)

// Scratch (static device globals — no allocation allowed)
__device__ float g_sumsP[ZSPLIT][BATCH * KTOT];
__device__ float g_sums[BATCH * KTOT];
__device__ float g_part[GSPLITK * BATCH * DM];

// ---------------------------------------------------------------------------
// Scalar FMA-pipe sincos (no MUFU): magic-number round, Cody-Waite pi/2
// reduction, deg-7 sin / deg-6 cos minimax, branch-free quadrant fixup.
// ---------------------------------------------------------------------------
__device__ __forceinline__ void sincos_poly(float th, float* so, float* co)
{
    const float MAGIC = 12582912.0f;              // 1.5 * 2^23
    float kf = fmaf(th, 0.63661977236758134f, MAGIC);
    const int q = __float_as_int(kf);
    kf -= MAGIC;
    float r = fmaf(kf, -1.5707962513e0f, th);
    r = fmaf(kf, -7.5497894159e-8f, r);
    const float u = r * r;
    float sp = -1.9515295891e-4f;
    sp = fmaf(sp, u,  8.3321608736e-3f);
    sp = fmaf(sp, u, -1.6666654611e-1f);
    sp = fmaf(sp * u, r, r);
    float cp = 2.443315711809948e-5f;
    cp = fmaf(cp, u, -1.388731625493765e-3f);
    cp = fmaf(cp, u,  4.166664568298827e-2f);
    cp = fmaf(cp, u, -0.5f);
    cp = fmaf(cp, u,  1.0f);
    const bool swap = (q & 1);
    float ss = swap ? cp : sp;
    float cc = swap ? sp : cp;
    const int sgn_s = (q & 2) << 30;
    const int sgn_c = ((q + 1) & 2) << 30;
    *so = __int_as_float(__float_as_int(ss) ^ sgn_s);
    *co = __int_as_float(__float_as_int(cc) ^ sgn_c);
}

// ---------------------------------------------------------------------------
// Phase 1 (R5 config, measured ~64us): 3 MUFU sincos + 1 FMA-pipe poly per d.
// Grid: (32, 8, 8) = 2048 blocks x 256 threads.
// ---------------------------------------------------------------------------
__global__ void __launch_bounds__(P1_THREADS) phase1_kernel(
    const float* __restrict__ xr, const float* __restrict__ xi,
    const float* __restrict__ W,  const float* __restrict__ Bm)
{
    __shared__ float xsT[DC][BT + 2];
    __shared__ float wbT[DC][2 * NT + 4];

    const int t  = threadIdx.x;
    const int tn = t & 15;
    const int tb = t >> 4;
    const int b0 = blockIdx.y * BT;
    const int n0 = blockIdx.x * NT;
    const int z  = blockIdx.z;
    const int d0 = z * DPER;

    #pragma unroll
    for (int i = t; i < BT * DC; i += P1_THREADS) {
        const int r = i >> 6;
        const int c = i & (DC - 1);
        const int gx = (b0 + r) * DM + d0 + c;
        xsT[c][r] = xr[gx] + xi[gx];
        const int gw = (n0 + r) * DM + d0 + c;
        const float winv = __fdividef(1.0f, 1.0f + fabsf(W[gw]));
        *(float2*)&wbT[c][2 * r] = make_float2(winv, Bm[gw]);
    }
    __syncthreads();

    float aS00 = 0.f, aS01 = 0.f, aS10 = 0.f, aS11 = 0.f;
    float aC00 = 0.f, aC01 = 0.f, aC10 = 0.f, aC11 = 0.f;

    #pragma unroll 8
    for (int d = 0; d < DC; d++) {
        const float2 xv = *(const float2*)&xsT[d][2 * tb];
        const float4 wb = *(const float4*)&wbT[d][4 * tn];
        float s, c;
        __sincosf(fmaf(xv.x, wb.x, wb.y), &s, &c); aS00 += s; aC00 += c;
        __sincosf(fmaf(xv.x, wb.z, wb.w), &s, &c); aS01 += s; aC01 += c;
        __sincosf(fmaf(xv.y, wb.x, wb.y), &s, &c); aS10 += s; aC10 += c;
        sincos_poly(fmaf(xv.y, wb.z, wb.w), &s, &c); aS11 += s; aC11 += c;
    }

    float* outp = g_sumsP[z];
    const int br0 = b0 + 2 * tb, br1 = br0 + 1;
    const int nc0 = n0 + 2 * tn;
    *(float2*)&outp[br0 * KTOT + nc0]      = make_float2(aC00, aC01);
    *(float2*)&outp[br1 * KTOT + nc0]      = make_float2(aC10, aC11);
    *(float2*)&outp[br0 * KTOT + NN + nc0] = make_float2(aS00, aS01);
    *(float2*)&outp[br1 * KTOT + NN + nc0] = make_float2(aS10, aS11);
}

// ---------------------------------------------------------------------------
// Combine the 8 d-slab partials. 2 threads per float4 output, shfl merge.
// ---------------------------------------------------------------------------
__global__ void __launch_bounds__(256) combine_kernel()
{
    const int t = threadIdx.x;
    const int zg = t & 1;
    const int o4 = blockIdx.x * 128 + (t >> 1);
    const int i  = o4 * 4;

    float4 v = make_float4(0.f, 0.f, 0.f, 0.f);
    #pragma unroll
    for (int j = 0; j < 4; j++) {
        const float4 p = *(const float4*)&g_sumsP[zg * 4 + j][i];
        v.x += p.x; v.y += p.y; v.z += p.z; v.w += p.w;
    }
    v.x += __shfl_xor_sync(0xFFFFFFFFu, v.x, 1);
    v.y += __shfl_xor_sync(0xFFFFFFFFu, v.y, 1);
    v.z += __shfl_xor_sync(0xFFFFFFFFu, v.z, 1);
    v.w += __shfl_xor_sync(0xFFFFFFFFu, v.w, 1);
    if (zg == 0) *(float4*)&g_sums[i] = v;
}

// ---------------------------------------------------------------------------
// Phase 2: 3xTF32 tensor-core split-K GEMM via nvcuda::wmma (m16n16k8).
//   out[b][m] = sum_k g_sums[b][k] * Wsel[m][k']
// Block: 128 threads = 4 warps (2x2 warp grid of 16x16 tiles) -> 32x32 tile.
// Grid: (DM/32=16, BATCH/32=8, GSPLITK=4) = 512 blocks.
// A,B split into tf32 hi + lo residual at staging; per k8: hh + lh + hl.
// ---------------------------------------------------------------------------
__global__ void __launch_bounds__(128) phase2_kernel(
    const float* __restrict__ PC, const float* __restrict__ PS)
{
    __shared__ float AsH[GBM][GLD], AsL[GBM][GLD];
    __shared__ float BsH[GBN][GLD], BsL[GBN][GLD];

    const int t   = threadIdx.x;
    const int wid = t >> 5;
    const int wm  = wid >> 1;         // warp row (0..1) -> 16 batch rows
    const int wn  = wid & 1;          // warp col (0..1) -> 16 out features
    const int m0 = blockIdx.x * GBN;
    const int b0 = blockIdx.y * GBM;
    const int z  = blockIdx.z;
    const int kbase = z * GKCHUNK;

    const float* __restrict__ Wsel = (kbase < NN) ? PC : PS;
    const int koff = (kbase < NN) ? 0 : NN;

    wmma::fragment<wmma::accumulator, 16, 16, 8, float> cFrag;
    wmma::fill_fragment(cFrag, 0.0f);

    for (int kw = kbase; kw < kbase + GKCHUNK; kw += GBK) {
        // Stage + hi/lo split: A (32x32) and B (32x32), 8 elems/thread each.
        #pragma unroll
        for (int j = 0; j < 8; j++) {
            const int idx = t + j * 128;
            const int r = idx >> 5, c = idx & 31;
            const float a = g_sums[(b0 + r) * KTOT + kw + c];
            const float ah = wmma::__float_to_tf32(a);
            AsH[r][c] = ah;
            AsL[r][c] = wmma::__float_to_tf32(a - ah);
            const float b = Wsel[(m0 + r) * NN + (kw + c - koff)];
            const float bh = wmma::__float_to_tf32(b);
            BsH[r][c] = bh;
            BsL[r][c] = wmma::__float_to_tf32(b - bh);
        }
        __syncthreads();

        #pragma unroll
        for (int k8 = 0; k8 < GBK; k8 += 8) {
            wmma::fragment<wmma::matrix_a, 16, 16, 8, wmma::precision::tf32,
                           wmma::row_major> aH, aL;
            wmma::fragment<wmma::matrix_b, 16, 16, 8, wmma::precision::tf32,
                           wmma::col_major> bH, bL;
            // A: rows [wm*16, +16), k cols [k8, +8), row-major ld=GLD
            wmma::load_matrix_sync(aH, &AsH[wm * 16][k8], GLD);
            wmma::load_matrix_sync(aL, &AsL[wm * 16][k8], GLD);
            // B stored [n][k] -> col-major (k x n) with ld=GLD
            wmma::load_matrix_sync(bH, &BsH[wn * 16][k8], GLD);
            wmma::load_matrix_sync(bL, &BsL[wn * 16][k8], GLD);

            wmma::mma_sync(cFrag, aH, bH, cFrag);   // hi*hi
            wmma::mma_sync(cFrag, aL, bH, cFrag);   // lo*hi
            wmma::mma_sync(cFrag, aH, bL, cFrag);   // hi*lo
        }
        __syncthreads();
    }

    float* outp = &g_part[z * BATCH * DM];
    wmma::store_matrix_sync(&outp[(b0 + wm * 16) * DM + m0 + wn * 16],
                            cFrag, DM, wmma::mem_row_major);
}

// ---------------------------------------------------------------------------
// Phase 3: reduce 4 split-K partials + SiLU. One float4 per thread.
// Grid: 128 blocks x 256 threads.
// ---------------------------------------------------------------------------
__global__ void __launch_bounds__(256) phase3_kernel(float* __restrict__ out)
{
    const int i = (blockIdx.x * 256 + threadIdx.x) * 4;
    if (i >= BATCH * DM) return;
    float4 v = make_float4(0.f, 0.f, 0.f, 0.f);
    #pragma unroll
    for (int zz = 0; zz < GSPLITK; zz++) {
        const float4 p = *(const float4*)&g_part[zz * BATCH * DM + i];
        v.x += p.x; v.y += p.y; v.z += p.z; v.w += p.w;
    }
    float4 o;
    o.x = v.x / (1.0f + __expf(-v.x));
    o.y = v.y / (1.0f + __expf(-v.y));
    o.z = v.z / (1.0f + __expf(-v.z));
    o.w = v.w / (1.0f + __expf(-v.w));
    *(float4*)&out[i] = o;
}

extern "C" void kernel_launch(void* const* d_in, const int* in_sizes, int n_in,
                              void* d_out, int out_size)
{
    (void)in_sizes; (void)n_in; (void)out_size;
    const float* xr = (const float*)d_in[0];
    const float* xi = (const float*)d_in[1];
    const float* W  = (const float*)d_in[2];
    const float* Bm = (const float*)d_in[3];
    const float* PC = (const float*)d_in[4];
    const float* PS = (const float*)d_in[5];
    float* out = (float*)d_out;

    dim3 g1(NN / NT, BATCH / BT, ZSPLIT);      // 2048 blocks
    phase1_kernel<<<g1, P1_THREADS>>>(xr, xi, W, Bm);

    combine_kernel<<<BATCH * KTOT / 4 / 128, 256>>>();   // 1024 blocks

    dim3 g2(DM / GBN, BATCH / GBM, GSPLITK);   // 16 x 8 x 4 = 512 blocks
    phase2_kernel<<<g2, 128>>>(PC, PS);

    phase3_kernel<<<BATCH * DM / 4 / 256, 256>>>(out);   // 128 blocks
}

// round 10
// speedup vs baseline: 1.2084x; 1.2084x over previous
#include <cuda_runtime.h>
#include <math.h>

// Problem dims (fixed by setup_inputs)
#define BATCH 256
#define DM    512
#define NN    1024
#define KTOT  (2*NN)

// Phase-1 tiling
#define BT 32
#define NT 32
#define DC 64
#define ZSPLIT 8
#define DPER (DM / ZSPLIT)       // 64 == DC
#define P1_THREADS 256

// Phase-2 tiling (split-K SGEMM, scalar FFMA)
#define BM 64
#define BN 64
#define BK 16
#define SPLITK 8
#define KCHUNK (KTOT / SPLITK)   // 256 (never crosses cos/sin boundary)

// Scratch (static device globals — no allocation allowed)
__device__ float g_sumsP[ZSPLIT][BATCH * KTOT];
__device__ float g_sums[BATCH * KTOT];
__device__ float g_part[SPLITK * BATCH * DM];

// ---------------------------------------------------------------------------
// FMA-pipe sincos, pi-based reduction (single sign fixup, ~18 issue slots):
// n = round(th/pi); r = th - n*pi (|r| <= pi/2); sin/cos deg-9/8 Taylor;
// sin(th) = (-1)^n sin(r), cos(th) = (-1)^n cos(r). Accuracy ~3e-5 abs worst
// case (validated R6: end-to-end rel_err 8.7e-7).
// ---------------------------------------------------------------------------
__device__ __forceinline__ void sincos_poly(float th, float* so, float* co)
{
    const float MAGIC = 12582912.0f;                   // 1.5 * 2^23
    float kf = fmaf(th, 0.3183098861837907f, MAGIC);   // th/pi + magic
    const int q = __float_as_int(kf);                  // low bits = n
    kf -= MAGIC;                                       // n as float
    float r = fmaf(kf, -3.14159274101f, th);           // th - n*fp32(pi)
    r = fmaf(kf, 8.7422776573e-8f, r);                 // + n*(fp32(pi)-pi)
    const float u = r * r;
    float sp = fmaf(2.7557319e-6f, u, -1.9841270e-4f);
    sp = fmaf(sp, u, 8.3333333e-3f);
    sp = fmaf(sp, u, -1.6666667e-1f);
    sp = fmaf(sp * u, r, r);                           // sin(r)
    float cp = fmaf(2.4801587e-5f, u, -1.3888889e-3f);
    cp = fmaf(cp, u, 4.1666667e-2f);
    cp = fmaf(cp, u, -0.5f);
    cp = fmaf(cp, u, 1.0f);                            // cos(r)
    const int g = q << 31;                             // (-1)^n as sign bit
    *so = __int_as_float(__float_as_int(sp) ^ g);
    *co = __int_as_float(__float_as_int(cp) ^ g);
}

// ---------------------------------------------------------------------------
// Phase 1: 3 MUFU sincos + 1 FMA-pipe poly per d (calibrated optimum mix).
// Grid: (32, 8, 8) = 2048 blocks x 256 threads.
// ---------------------------------------------------------------------------
__global__ void __launch_bounds__(P1_THREADS) phase1_kernel(
    const float* __restrict__ xr, const float* __restrict__ xi,
    const float* __restrict__ W,  const float* __restrict__ Bm)
{
    __shared__ float xsT[DC][BT + 2];
    __shared__ float wbT[DC][2 * NT + 4];

    const int t  = threadIdx.x;
    const int tn = t & 15;
    const int tb = t >> 4;
    const int b0 = blockIdx.y * BT;
    const int n0 = blockIdx.x * NT;
    const int z  = blockIdx.z;
    const int d0 = z * DPER;

    #pragma unroll
    for (int i = t; i < BT * DC; i += P1_THREADS) {
        const int r = i >> 6;
        const int c = i & (DC - 1);
        const int gx = (b0 + r) * DM + d0 + c;
        xsT[c][r] = xr[gx] + xi[gx];
        const int gw = (n0 + r) * DM + d0 + c;
        const float winv = __fdividef(1.0f, 1.0f + fabsf(W[gw]));
        *(float2*)&wbT[c][2 * r] = make_float2(winv, Bm[gw]);
    }
    __syncthreads();

    float aS00 = 0.f, aS01 = 0.f, aS10 = 0.f, aS11 = 0.f;
    float aC00 = 0.f, aC01 = 0.f, aC10 = 0.f, aC11 = 0.f;

    #pragma unroll 8
    for (int d = 0; d < DC; d++) {
        const float2 xv = *(const float2*)&xsT[d][2 * tb];
        const float4 wb = *(const float4*)&wbT[d][4 * tn];
        float s, c;
        __sincosf(fmaf(xv.x, wb.x, wb.y), &s, &c); aS00 += s; aC00 += c;
        __sincosf(fmaf(xv.x, wb.z, wb.w), &s, &c); aS01 += s; aC01 += c;
        __sincosf(fmaf(xv.y, wb.x, wb.y), &s, &c); aS10 += s; aC10 += c;
        sincos_poly(fmaf(xv.y, wb.z, wb.w), &s, &c); aS11 += s; aC11 += c;
    }

    float* outp = g_sumsP[z];
    const int br0 = b0 + 2 * tb, br1 = br0 + 1;
    const int nc0 = n0 + 2 * tn;
    *(float2*)&outp[br0 * KTOT + nc0]      = make_float2(aC00, aC01);
    *(float2*)&outp[br1 * KTOT + nc0]      = make_float2(aC10, aC11);
    *(float2*)&outp[br0 * KTOT + NN + nc0] = make_float2(aS00, aS01);
    *(float2*)&outp[br1 * KTOT + NN + nc0] = make_float2(aS10, aS11);
}

// ---------------------------------------------------------------------------
// Combine the 8 d-slab partials. 2 threads per float4 output, shfl merge.
// ---------------------------------------------------------------------------
__global__ void __launch_bounds__(256) combine_kernel()
{
    const int t = threadIdx.x;
    const int zg = t & 1;
    const int o4 = blockIdx.x * 128 + (t >> 1);
    const int i  = o4 * 4;

    float4 v = make_float4(0.f, 0.f, 0.f, 0.f);
    #pragma unroll
    for (int j = 0; j < 4; j++) {
        const float4 p = *(const float4*)&g_sumsP[zg * 4 + j][i];
        v.x += p.x; v.y += p.y; v.z += p.z; v.w += p.w;
    }
    v.x += __shfl_xor_sync(0xFFFFFFFFu, v.x, 1);
    v.y += __shfl_xor_sync(0xFFFFFFFFu, v.y, 1);
    v.z += __shfl_xor_sync(0xFFFFFFFFu, v.z, 1);
    v.w += __shfl_xor_sync(0xFFFFFFFFu, v.w, 1);
    if (zg == 0) *(float4*)&g_sums[i] = v;
}

// ---------------------------------------------------------------------------
// Phase 2: split-K SGEMM, scalar FFMA, 4x4 per thread.
// Grid: (DM/64=8, BATCH/64=4, SPLITK=8) = 256 blocks x 256 threads.
// ---------------------------------------------------------------------------
__global__ void __launch_bounds__(256) phase2_kernel(
    const float* __restrict__ PC, const float* __restrict__ PS)
{
    __shared__ float As[BK][BM + 4];
    __shared__ float Bs[BK][BN + 4];

    const int t  = threadIdx.x;
    const int tx = t & 15;
    const int ty = t >> 4;
    const int m0 = blockIdx.x * BN;
    const int b0 = blockIdx.y * BM;
    const int z  = blockIdx.z;
    const int kbase = z * KCHUNK;

    const float* __restrict__ Wsel = (kbase < NN) ? PC : PS;
    const int koff = (kbase < NN) ? 0 : NN;

    float acc[4][4];
    #pragma unroll
    for (int i = 0; i < 4; i++)
        #pragma unroll
        for (int j = 0; j < 4; j++) acc[i][j] = 0.0f;

    for (int k0 = kbase; k0 < kbase + KCHUNK; k0 += BK) {
        #pragma unroll
        for (int i = t; i < BM * BK; i += 256) {
            const int r  = i >> 4;
            const int kk = i & 15;
            As[kk][r] = g_sums[(b0 + r) * KTOT + k0 + kk];
        }
        #pragma unroll
        for (int i = t; i < BN * BK; i += 256) {
            const int r  = i >> 4;
            const int kk = i & 15;
            Bs[kk][r] = Wsel[(m0 + r) * NN + (k0 + kk - koff)];
        }
        __syncthreads();

        #pragma unroll
        for (int kk = 0; kk < BK; kk++) {
            const float4 av = *(const float4*)&As[kk][ty * 4];
            const float4 bv = *(const float4*)&Bs[kk][tx * 4];
            const float a[4] = {av.x, av.y, av.z, av.w};
            const float b[4] = {bv.x, bv.y, bv.z, bv.w};
            #pragma unroll
            for (int i = 0; i < 4; i++)
                #pragma unroll
                for (int j = 0; j < 4; j++)
                    acc[i][j] = fmaf(a[i], b[j], acc[i][j]);
        }
        __syncthreads();
    }

    float* outp = &g_part[z * BATCH * DM];
    #pragma unroll
    for (int i = 0; i < 4; i++)
        *(float4*)&outp[(b0 + ty * 4 + i) * DM + m0 + tx * 4] =
            make_float4(acc[i][0], acc[i][1], acc[i][2], acc[i][3]);
}

// ---------------------------------------------------------------------------
// Phase 3: reduce 8 split-K partials + SiLU. 2 threads per float4 output,
// 4 slabs each, shfl merge. Grid: 256 blocks x 256 threads.
// ---------------------------------------------------------------------------
__global__ void __launch_bounds__(256) phase3_kernel(float* __restrict__ out)
{
    const int t  = threadIdx.x;
    const int zg = t & 1;
    const int o4 = blockIdx.x * 128 + (t >> 1);
    const int i  = o4 * 4;

    float4 v = make_float4(0.f, 0.f, 0.f, 0.f);
    #pragma unroll
    for (int j = 0; j < 4; j++) {
        const float4 p = *(const float4*)&g_part[(zg * 4 + j) * BATCH * DM + i];
        v.x += p.x; v.y += p.y; v.z += p.z; v.w += p.w;
    }
    v.x += __shfl_xor_sync(0xFFFFFFFFu, v.x, 1);
    v.y += __shfl_xor_sync(0xFFFFFFFFu, v.y, 1);
    v.z += __shfl_xor_sync(0xFFFFFFFFu, v.z, 1);
    v.w += __shfl_xor_sync(0xFFFFFFFFu, v.w, 1);
    if (zg == 0) {
        float4 o;
        o.x = v.x / (1.0f + __expf(-v.x));
        o.y = v.y / (1.0f + __expf(-v.y));
        o.z = v.z / (1.0f + __expf(-v.z));
        o.w = v.w / (1.0f + __expf(-v.w));
        *(float4*)&out[i] = o;
    }
}

extern "C" void kernel_launch(void* const* d_in, const int* in_sizes, int n_in,
                              void* d_out, int out_size)
{
    (void)in_sizes; (void)n_in; (void)out_size;
    const float* xr = (const float*)d_in[0];
    const float* xi = (const float*)d_in[1];
    const float* W  = (const float*)d_in[2];
    const float* Bm = (const float*)d_in[3];
    const float* PC = (const float*)d_in[4];
    const float* PS = (const float*)d_in[5];
    float* out = (float*)d_out;

    dim3 g1(NN / NT, BATCH / BT, ZSPLIT);      // 2048 blocks
    phase1_kernel<<<g1, P1_THREADS>>>(xr, xi, W, Bm);

    combine_kernel<<<BATCH * KTOT / 4 / 128, 256>>>();   // 1024 blocks

    dim3 g2(DM / BN, BATCH / BM, SPLITK);      // 8 x 4 x 8 = 256 blocks
    phase2_kernel<<<g2, 256>>>(PC, PS);

    phase3_kernel<<<BATCH * DM / 4 / 128, 256>>>(out);   // 256 blocks
}

// round 11
// speedup vs baseline: 1.2358x; 1.0227x over previous
#include <cuda_runtime.h>
#include <math.h>

// Problem dims (fixed by setup_inputs)
#define BATCH 256
#define DM    512
#define NN    1024
#define KTOT  (2*NN)

// Phase-1 tiling
#define BT 32
#define NT 32
#define DC 64
#define ZSPLIT 8
#define DPER (DM / ZSPLIT)       // 64 == DC
#define P1_THREADS 256

// Phase-2 tiling (split-K SGEMM, scalar FFMA)
#define BM 64
#define BN 64
#define BK 16
#define SPLITK 16
#define KCHUNK (KTOT / SPLITK)   // 128 (never crosses cos/sin boundary)

// Scratch (static device globals — no allocation allowed)
__device__ float g_sumsP[ZSPLIT][BATCH * KTOT];
__device__ float g_sums[BATCH * KTOT];
__device__ float g_part[SPLITK * BATCH * DM];

// ---------------------------------------------------------------------------
// FMA-pipe sincos, pi-based reduction, single-step CW (n<=4 here, so the
// dropped lo-term contributes <= 3.5e-7 to r): ~17 issue slots.
// ---------------------------------------------------------------------------
__device__ __forceinline__ void sincos_poly(float th, float* so, float* co)
{
    const float MAGIC = 12582912.0f;                   // 1.5 * 2^23
    float kf = fmaf(th, 0.3183098861837907f, MAGIC);   // th/pi + magic
    const int q = __float_as_int(kf);                  // low bits = n
    kf -= MAGIC;                                       // n as float
    const float r = fmaf(kf, -3.14159265358979f, th);  // th - n*pi
    const float u = r * r;
    float sp = fmaf(2.7557319e-6f, u, -1.9841270e-4f);
    sp = fmaf(sp, u, 8.3333333e-3f);
    sp = fmaf(sp, u, -1.6666667e-1f);
    sp = fmaf(sp * u, r, r);                           // sin(r)
    float cp = fmaf(2.4801587e-5f, u, -1.3888889e-3f);
    cp = fmaf(cp, u, 4.1666667e-2f);
    cp = fmaf(cp, u, -0.5f);
    cp = fmaf(cp, u, 1.0f);                            // cos(r)
    const int g = q << 31;                             // (-1)^n sign bit
    *so = __int_as_float(__float_as_int(sp) ^ g);
    *co = __int_as_float(__float_as_int(cp) ^ g);
}

// ---------------------------------------------------------------------------
// Phase 1: 3 MUFU sincos + 1 FMA-pipe poly per d (calibrated optimum mix).
// Grid: (32, 8, 8) = 2048 blocks x 256 threads.
// ---------------------------------------------------------------------------
__global__ void __launch_bounds__(P1_THREADS) phase1_kernel(
    const float* __restrict__ xr, const float* __restrict__ xi,
    const float* __restrict__ W,  const float* __restrict__ Bm)
{
    __shared__ float xsT[DC][BT + 2];
    __shared__ float wbT[DC][2 * NT + 4];

    const int t  = threadIdx.x;
    const int tn = t & 15;
    const int tb = t >> 4;
    const int b0 = blockIdx.y * BT;
    const int n0 = blockIdx.x * NT;
    const int z  = blockIdx.z;
    const int d0 = z * DPER;

    #pragma unroll
    for (int i = t; i < BT * DC; i += P1_THREADS) {
        const int r = i >> 6;
        const int c = i & (DC - 1);
        const int gx = (b0 + r) * DM + d0 + c;
        xsT[c][r] = xr[gx] + xi[gx];
        const int gw = (n0 + r) * DM + d0 + c;
        const float winv = __fdividef(1.0f, 1.0f + fabsf(W[gw]));
        *(float2*)&wbT[c][2 * r] = make_float2(winv, Bm[gw]);
    }
    __syncthreads();

    float aS00 = 0.f, aS01 = 0.f, aS10 = 0.f, aS11 = 0.f;
    float aC00 = 0.f, aC01 = 0.f, aC10 = 0.f, aC11 = 0.f;

    #pragma unroll 8
    for (int d = 0; d < DC; d++) {
        const float2 xv = *(const float2*)&xsT[d][2 * tb];
        const float4 wb = *(const float4*)&wbT[d][4 * tn];
        float s, c;
        __sincosf(fmaf(xv.x, wb.x, wb.y), &s, &c); aS00 += s; aC00 += c;
        __sincosf(fmaf(xv.x, wb.z, wb.w), &s, &c); aS01 += s; aC01 += c;
        __sincosf(fmaf(xv.y, wb.x, wb.y), &s, &c); aS10 += s; aC10 += c;
        sincos_poly(fmaf(xv.y, wb.z, wb.w), &s, &c); aS11 += s; aC11 += c;
    }

    float* outp = g_sumsP[z];
    const int br0 = b0 + 2 * tb, br1 = br0 + 1;
    const int nc0 = n0 + 2 * tn;
    *(float2*)&outp[br0 * KTOT + nc0]      = make_float2(aC00, aC01);
    *(float2*)&outp[br1 * KTOT + nc0]      = make_float2(aC10, aC11);
    *(float2*)&outp[br0 * KTOT + NN + nc0] = make_float2(aS00, aS01);
    *(float2*)&outp[br1 * KTOT + NN + nc0] = make_float2(aS10, aS11);
}

// ---------------------------------------------------------------------------
// Combine the 8 d-slab partials. 2 threads per float4 output, shfl merge.
// ---------------------------------------------------------------------------
__global__ void __launch_bounds__(256) combine_kernel()
{
    const int t = threadIdx.x;
    const int zg = t & 1;
    const int o4 = blockIdx.x * 128 + (t >> 1);
    const int i  = o4 * 4;

    float4 v = make_float4(0.f, 0.f, 0.f, 0.f);
    #pragma unroll
    for (int j = 0; j < 4; j++) {
        const float4 p = *(const float4*)&g_sumsP[zg * 4 + j][i];
        v.x += p.x; v.y += p.y; v.z += p.z; v.w += p.w;
    }
    v.x += __shfl_xor_sync(0xFFFFFFFFu, v.x, 1);
    v.y += __shfl_xor_sync(0xFFFFFFFFu, v.y, 1);
    v.z += __shfl_xor_sync(0xFFFFFFFFu, v.z, 1);
    v.w += __shfl_xor_sync(0xFFFFFFFFu, v.w, 1);
    if (zg == 0) *(float4*)&g_sums[i] = v;
}

// ---------------------------------------------------------------------------
// Phase 2: split-K SGEMM, scalar FFMA, 4x4 per thread.
// Grid: (DM/64=8, BATCH/64=4, SPLITK=16) = 512 blocks x 256 threads.
// ---------------------------------------------------------------------------
__global__ void __launch_bounds__(256) phase2_kernel(
    const float* __restrict__ PC, const float* __restrict__ PS)
{
    __shared__ float As[BK][BM + 4];
    __shared__ float Bs[BK][BN + 4];

    const int t  = threadIdx.x;
    const int tx = t & 15;
    const int ty = t >> 4;
    const int m0 = blockIdx.x * BN;
    const int b0 = blockIdx.y * BM;
    const int z  = blockIdx.z;
    const int kbase = z * KCHUNK;

    const float* __restrict__ Wsel = (kbase < NN) ? PC : PS;
    const int koff = (kbase < NN) ? 0 : NN;

    float acc[4][4];
    #pragma unroll
    for (int i = 0; i < 4; i++)
        #pragma unroll
        for (int j = 0; j < 4; j++) acc[i][j] = 0.0f;

    for (int k0 = kbase; k0 < kbase + KCHUNK; k0 += BK) {
        #pragma unroll
        for (int i = t; i < BM * BK; i += 256) {
            const int r  = i >> 4;
            const int kk = i & 15;
            As[kk][r] = g_sums[(b0 + r) * KTOT + k0 + kk];
        }
        #pragma unroll
        for (int i = t; i < BN * BK; i += 256) {
            const int r  = i >> 4;
            const int kk = i & 15;
            Bs[kk][r] = Wsel[(m0 + r) * NN + (k0 + kk - koff)];
        }
        __syncthreads();

        #pragma unroll
        for (int kk = 0; kk < BK; kk++) {
            const float4 av = *(const float4*)&As[kk][ty * 4];
            const float4 bv = *(const float4*)&Bs[kk][tx * 4];
            const float a[4] = {av.x, av.y, av.z, av.w};
            const float b[4] = {bv.x, bv.y, bv.z, bv.w};
            #pragma unroll
            for (int i = 0; i < 4; i++)
                #pragma unroll
                for (int j = 0; j < 4; j++)
                    acc[i][j] = fmaf(a[i], b[j], acc[i][j]);
        }
        __syncthreads();
    }

    float* outp = &g_part[z * BATCH * DM];
    #pragma unroll
    for (int i = 0; i < 4; i++)
        *(float4*)&outp[(b0 + ty * 4 + i) * DM + m0 + tx * 4] =
            make_float4(acc[i][0], acc[i][1], acc[i][2], acc[i][3]);
}

// ---------------------------------------------------------------------------
// Phase 3: reduce 16 split-K partials + SiLU. 4 threads per float4 output,
// 4 slabs each, shfl merge. Grid: 512 blocks x 256 threads.
// ---------------------------------------------------------------------------
__global__ void __launch_bounds__(256) phase3_kernel(float* __restrict__ out)
{
    const int t  = threadIdx.x;
    const int zg = t & 3;
    const int o4 = blockIdx.x * 64 + (t >> 2);
    const int i  = o4 * 4;

    float4 v = make_float4(0.f, 0.f, 0.f, 0.f);
    #pragma unroll
    for (int j = 0; j < 4; j++) {
        const float4 p = *(const float4*)&g_part[(zg * 4 + j) * BATCH * DM + i];
        v.x += p.x; v.y += p.y; v.z += p.z; v.w += p.w;
    }
    #pragma unroll
    for (int m = 1; m <= 2; m <<= 1) {
        v.x += __shfl_xor_sync(0xFFFFFFFFu, v.x, m);
        v.y += __shfl_xor_sync(0xFFFFFFFFu, v.y, m);
        v.z += __shfl_xor_sync(0xFFFFFFFFu, v.z, m);
        v.w += __shfl_xor_sync(0xFFFFFFFFu, v.w, m);
    }
    if (zg == 0) {
        float4 o;
        o.x = v.x / (1.0f + __expf(-v.x));
        o.y = v.y / (1.0f + __expf(-v.y));
        o.z = v.z / (1.0f + __expf(-v.z));
        o.w = v.w / (1.0f + __expf(-v.w));
        *(float4*)&out[i] = o;
    }
}

extern "C" void kernel_launch(void* const* d_in, const int* in_sizes, int n_in,
                              void* d_out, int out_size)
{
    (void)in_sizes; (void)n_in; (void)out_size;
    const float* xr = (const float*)d_in[0];
    const float* xi = (const float*)d_in[1];
    const float* W  = (const float*)d_in[2];
    const float* Bm = (const float*)d_in[3];
    const float* PC = (const float*)d_in[4];
    const float* PS = (const float*)d_in[5];
    float* out = (float*)d_out;

    dim3 g1(NN / NT, BATCH / BT, ZSPLIT);      // 2048 blocks
    phase1_kernel<<<g1, P1_THREADS>>>(xr, xi, W, Bm);

    combine_kernel<<<BATCH * KTOT / 4 / 128, 256>>>();   // 1024 blocks

    dim3 g2(DM / BN, BATCH / BM, SPLITK);      // 8 x 4 x 16 = 512 blocks
    phase2_kernel<<<g2, 256>>>(PC, PS);

    phase3_kernel<<<BATCH * DM / 4 / 64, 256>>>(out);    // 512 blocks
}